// round 1
// baseline (speedup 1.0000x reference)
#include <cuda_runtime.h>

#define NN     256
#define NS     512
#define MAXSP  32
#define NSTEPS 32
#define VRESET 1.0f

__device__ __forceinline__ float sigmoidf_(float x) {
    return 1.0f / (1.0f + expf(-x));
}

__global__ void __launch_bounds__(NN) snn_kernel(
    const float* __restrict__ input_current,  // [NN]
    const float* __restrict__ w,              // [NN, NN]
    const float* __restrict__ mu,             // [2]
    const float* __restrict__ v0,             // [NN]
    const float* __restrict__ i0,             // [NN]
    const float* __restrict__ s0,             // [NS, NN]
    const float* __restrict__ reset_s,        // [MAXSP, NS, NN]
    const int*   __restrict__ t1_raw,
    float* __restrict__ out_times,            // [NS, MAXSP]
    float* __restrict__ out_vals,             // [NS, MAXSP, NN, 3]
    float* __restrict__ out_marks)            // [NS, MAXSP, NN]
{
    const int s    = blockIdx.x;
    const int n    = threadIdx.x;
    const int warp = n >> 5;
    const int lane = n & 31;

    __shared__ float red_v[8];
    __shared__ int   red_i[8];
    __shared__ float bcast_v;
    __shared__ int   bcast_i;
    __shared__ float sp_sh, sn_sh;
    __shared__ unsigned em_ballot[8];

    // t1 dtype sniffing: small positive int -> integer payload (int32 or low
    // word of int64); otherwise reinterpret the bits as float32.
    float t1f;
    {
        int iv = t1_raw[0];
        if (iv > 0 && iv < 1000000) t1f = (float)iv;
        else                        t1f = __int_as_float(iv);
    }

    const float ic  = input_current[n];
    const float mu1 = mu[0];
    const float mu2 = mu[1];

    float v   = v0[n];
    float ii  = i0[n];
    float sv  = s0[s * NN + n];
    float t0s = 0.0f;

    for (int k = 0; k < MAXSP; ++k) {
        const float dt = (t1f - t0s) / (float)NSTEPS;
        const float h  = dt;

        float tev = t1f;
        float yv = v, yi = ii, ys = sv;   // current state within the round
        bool  trig = false;
        bool  em   = false;
        float ev_v, ev_i, ev_s;           // event / end-of-round state

        if (dt != 0.0f) {
            float t = t0s;
            for (int step = 0; step < NSTEPS; ++step) {
                // ---- RK4 (mirror reference op order) ----
                float k1v = mu1 * ((yi + ic) - yv);
                float k1i = -mu2 * yi;
                float k1s = sigmoidf_(yv);
                float hh  = 0.5f * h;
                float v2 = yv + hh * k1v, i2 = yi + hh * k1i;
                float k2v = mu1 * ((i2 + ic) - v2);
                float k2i = -mu2 * i2;
                float k2s = sigmoidf_(v2);
                float v3 = yv + hh * k2v, i3 = yi + hh * k2i;
                float k3v = mu1 * ((i3 + ic) - v3);
                float k3i = -mu2 * i3;
                float k3s = sigmoidf_(v3);
                float v4 = yv + h * k3v, i4 = yi + h * k3i;
                float k4v = mu1 * ((i4 + ic) - v4);
                float k4i = -mu2 * i4;
                float k4s = sigmoidf_(v4);
                float h6 = h / 6.0f;
                float nv = yv + h6 * (k1v + 2.0f * k2v + 2.0f * k3v + k4v);
                float ni = yi + h6 * (k1i + 2.0f * k2i + 2.0f * k3i + k4i);
                float ns = ys + h6 * (k1s + 2.0f * k2s + 2.0f * k3s + k4s);

                // ---- block argmax(s_new), first-index tie-break ----
                float bv = ns; int bi = n;
                #pragma unroll
                for (int o = 16; o > 0; o >>= 1) {
                    float ov = __shfl_down_sync(0xffffffffu, bv, o);
                    int   oi = __shfl_down_sync(0xffffffffu, bi, o);
                    if (ov > bv || (ov == bv && oi < bi)) { bv = ov; bi = oi; }
                }
                if (lane == 0) { red_v[warp] = bv; red_i[warp] = bi; }
                __syncthreads();
                if (n == 0) {
                    float mv = red_v[0]; int mi = red_i[0];
                    #pragma unroll
                    for (int ww = 1; ww < 8; ++ww) {
                        float ov = red_v[ww]; int oi = red_i[ww];
                        if (ov > mv || (ov == mv && oi < mi)) { mv = ov; mi = oi; }
                    }
                    bcast_v = mv; bcast_i = mi;
                }
                __syncthreads();
                const float mv = bcast_v;
                const int   mi = bcast_i;

                if (mv > 0.0f) {   // trigger — uniform across block
                    if (n == mi) { sp_sh = ys; sn_sh = ns; }
                    __syncthreads();
                    const float sp = sp_sh, sn = sn_sh;
                    float frac = sp / (sp - sn + 1e-12f);
                    frac = fminf(fmaxf(frac, 0.0f), 1.0f);
                    tev  = t + frac * dt;
                    ev_v = yv + frac * (nv - yv);
                    ev_i = yi + frac * (ni - yi);
                    ev_s = ys + frac * (ns - ys);
                    em   = (ns > 0.0f);
                    trig = true;
                    break;
                }
                yv = nv; yi = ni; ys = ns;
                t += dt;
            }
        }
        if (!trig) { ev_v = yv; ev_i = yi; ev_s = ys; }

        // ---- outputs ----
        if (n == 0) out_times[s * MAXSP + k] = tev;
        {
            const long row  = (long)(s * MAXSP + k);
            const long base = (row * NN + n) * 3;
            out_vals[base + 0] = ev_v;
            out_vals[base + 1] = ev_i;
            out_vals[base + 2] = ev_s;
            out_marks[row * NN + n] = em ? 1.0f : 0.0f;
        }

        // ---- next-round state ----
        if (trig) {
            unsigned b = __ballot_sync(0xffffffffu, em);
            if (lane == 0) em_ballot[warp] = b;
            __syncthreads();
            int eidx = 0;
            #pragma unroll
            for (int ww = 0; ww < 8; ++ww) {
                unsigned bb = em_ballot[ww];
                if (bb) { eidx = ww * 32 + __ffs(bb) - 1; break; }
            }
            v  = ev_v - (em ? VRESET : 0.0f);
            ii = ev_i + w[eidx * NN + n];
            const float rs = reset_s[((long)k * NS + s) * NN + n];
            sv = fminf(em ? rs : ev_s, 0.0f);
        } else {
            v  = ev_v;
            ii = ev_i;
            sv = fminf(ev_s, 0.0f);
        }
        t0s = tev;
        __syncthreads();  // protect smem reuse across rounds
    }
}

extern "C" void kernel_launch(void* const* d_in, const int* in_sizes, int n_in,
                              void* d_out, int out_size) {
    const float* input_current = (const float*)d_in[0];
    const float* w             = (const float*)d_in[1];
    const float* mu            = (const float*)d_in[2];
    const float* v0            = (const float*)d_in[3];
    const float* i0            = (const float*)d_in[4];
    const float* s0            = (const float*)d_in[5];
    const float* reset_s       = (const float*)d_in[6];
    const int*   t1            = (const int*)  d_in[7];

    float* out = (float*)d_out;
    float* out_times = out;                                      // 512*32
    float* out_vals  = out + (long)NS * MAXSP;                   // 512*32*256*3
    float* out_marks = out + (long)NS * MAXSP
                           + (long)NS * MAXSP * NN * 3;          // 512*32*256

    snn_kernel<<<NS, NN>>>(input_current, w, mu, v0, i0, s0, reset_s, t1,
                           out_times, out_vals, out_marks);
}